// round 12
// baseline (speedup 1.0000x reference)
#include <cuda_runtime.h>

#define NT   256          // threads per CTA
#define VPT  8            // float4 vectors per thread (8*4*256 = 8192)
#define COLS 8192         // row length
#define GCAP 128          // gather capacity for the hit bin

// Monotone mapping: float -> uint32 such that float order == unsigned order.
__device__ __forceinline__ unsigned mono(float f) {
    unsigned u = __float_as_uint(f);
    return (u & 0x80000000u) ? ~u : (u | 0x80000000u);
}

// Inverse of mono(). Clamps NaN bit patterns to +-inf.
__device__ __forceinline__ float inv_mono(unsigned k) {
    unsigned u = (k & 0x80000000u) ? (k & 0x7FFFFFFFu) : ~k;
    if ((u & 0x7F800000u) == 0x7F800000u && (u & 0x007FFFFFu))
        u = (u & 0x80000000u) | 0x7F800000u;
    return __uint_as_float(u);
}

// Single-warp collective: walk a 1024-bin histogram from the TOP bin down, find
// the bin where the cumulative count first reaches rr. All 32 lanes must call.
__device__ __forceinline__ void rank_walk(const unsigned* hist, unsigned rr, int lane,
                                          unsigned& bin_out, unsigned& nr_out) {
    const int base = 1024 - 32 * (lane + 1);   // lane 0 owns the TOP 32 bins
    unsigned s = 0;
#pragma unroll
    for (int i = 0; i < 32; i++) s += hist[base + i];
    unsigned p = s, t;
    t = __shfl_up_sync(0xFFFFFFFFu, p, 1);  if (lane >= 1)  p += t;
    t = __shfl_up_sync(0xFFFFFFFFu, p, 2);  if (lane >= 2)  p += t;
    t = __shfl_up_sync(0xFFFFFFFFu, p, 4);  if (lane >= 4)  p += t;
    t = __shfl_up_sync(0xFFFFFFFFu, p, 8);  if (lane >= 8)  p += t;
    t = __shfl_up_sync(0xFFFFFFFFu, p, 16); if (lane >= 16) p += t;
    const unsigned excl = p - s;
    const bool hit = (excl < rr) && (rr <= p);
    const unsigned m = __ballot_sync(0xFFFFFFFFu, hit);
    unsigned bin = 0, nr = rr;
    if (m) {
        const int hl = __ffs(m) - 1;
        if (lane == hl) {
            unsigned cum = excl;
            for (int b = base + 31; b >= base; b--) {
                cum += hist[b];
                if (cum >= rr) { bin = (unsigned)b; nr = rr - (cum - hist[b]); break; }
            }
        }
        bin = __shfl_sync(0xFFFFFFFFu, bin, hl);
        nr  = __shfl_sync(0xFFFFFFFFu, nr, hl);
    }
    bin_out = bin; nr_out = nr;
}

__global__ void __launch_bounds__(NT, 4) ksparse_kernel(const float* __restrict__ in,
                                                        const int* __restrict__ kp,
                                                        float* __restrict__ out) {
    __shared__ unsigned hist[1024];    // 4 KB
    __shared__ unsigned g[GCAP];       // hit-bin gather
    __shared__ int s_cnt, s_gn;
    __shared__ unsigned s_bin, s_rank;
    __shared__ float s_T;

    const int tid  = threadIdx.x;
    const int lane = tid & 31;
    const int wid  = tid >> 5;

    const float4* rp = (const float4*)(in  + (size_t)blockIdx.x * COLS);
    float4*       op = (float4*)      (out + (size_t)blockIdx.x * COLS);

    // Entire row resident in registers: one global read.
    float4 v[VPT];
#pragma unroll
    for (int i = 0; i < VPT; i++) v[i] = rp[tid + i * NT];

    const int K = kp ? __ldg(kp) : 512;
    const unsigned r = (unsigned)(K + 1);   // rank of threshold (descending, 1-indexed)

    // ---- Analytic pivot: U_lo below T with large margin (no samples needed).
    // Distribution assumption affects ONLY performance; guards route any
    // mismatch to the exact fallback.
    float p = (2.5f * (float)r + 160.0f) / (float)COLS;
    p = fminf(0.499f, fmaxf(p, 0.015625f));
    const float U_lo = normcdfinvf(1.0f - p);
    const unsigned klo = mono(U_lo);

    // Zero per-row state.
    hist[tid] = 0; hist[tid + NT] = 0; hist[tid + 2 * NT] = 0; hist[tid + 3 * NT] = 0;
    if (tid == 0) { s_cnt = 0; s_gn = 0; }

    // ---- Phase 3: candidate mask + register-direct histogram ----
    unsigned mbr = 0;
#pragma unroll
    for (int i = 0; i < VPT; i++) {
#pragma unroll
        for (int j = 0; j < 4; j++)
            mbr |= ((unsigned)((&v[i].x)[j] > U_lo)) << (i * 4 + j);
    }
    // nbuf total: popc -> warp reduce -> one atomic per warp.
    int cnt = __popc(mbr);
#pragma unroll
    for (int off = 16; off; off >>= 1) cnt += __shfl_down_sync(0xFFFFFFFFu, cnt, off);
    __syncthreads();                       // hist/s_cnt zeroing visible to all
    if (lane == 0) atomicAdd(&s_cnt, cnt);
    // Histogram candidates straight from registers (clamped 10-bit digit).
#pragma unroll
    for (int i = 0; i < VPT; i++) {
#pragma unroll
        for (int j = 0; j < 4; j++) {
            if ((mbr >> (i * 4 + j)) & 1u) {
                unsigned dig = (mono((&v[i].x)[j]) - klo) >> 14;
                dig = dig > 1023u ? 1023u : dig;   // clamp: monotone for huge keys
                atomicAdd(&hist[dig], 1u);
            }
        }
    }
    __syncthreads();

    const int nbuf = s_cnt;
    const bool ok = ((int)r <= nbuf);
    bool need_fb = !ok;                            // block-uniform

    if (ok) {
        // ---- Phase 4a: rank r over the 1024-bin histogram ----
        if (wid == 0) {
            unsigned b, nr;
            rank_walk(hist, r, lane, b, nr);
            if (lane == 0) { s_bin = b; s_rank = nr; }
        }
        __syncthreads();
        const unsigned bin = s_bin;
        const unsigned nr  = s_rank;
        const int m = (int)hist[bin];
        if (m <= GCAP) {
            // ---- Phase 4b: gather hit-bin keys from registers ----
#pragma unroll
            for (int i = 0; i < VPT; i++) {
#pragma unroll
                for (int j = 0; j < 4; j++) {
                    if ((mbr >> (i * 4 + j)) & 1u) {
                        const unsigned d = mono((&v[i].x)[j]) - klo;
                        unsigned dig = d >> 14;
                        dig = dig > 1023u ? 1023u : dig;
                        if (dig == bin) {
                            const int pg = atomicAdd(&s_gn, 1);
                            if (pg < GCAP) g[pg] = d;
                        }
                    }
                }
            }
            __syncthreads();
            // ---- Phase 4c: warp 0 selects the nr-th largest among m keys ----
            if (wid == 0) {
                unsigned my[4]; int gt[4] = {0,0,0,0}, ge[4] = {0,0,0,0};
#pragma unroll
                for (int q = 0; q < 4; q++)
                    my[q] = (lane + 32 * q < m) ? g[lane + 32 * q] : 0u;
                for (int i = 0; i < m; i++) {
                    const unsigned ki = g[i];
#pragma unroll
                    for (int q = 0; q < 4; q++) {
                        gt[q] += (ki > my[q]);
                        ge[q] += (ki >= my[q]);
                    }
                }
                bool found = false; unsigned sel = 0;
#pragma unroll
                for (int q = 0; q < 4; q++) {
                    const bool hit = (lane + 32 * q < m) &&
                                     ((unsigned)gt[q] < nr) && (nr <= (unsigned)ge[q]);
                    if (hit && !found) { sel = my[q]; found = true; }
                }
                const unsigned bm = __ballot_sync(0xFFFFFFFFu, found);
                if (bm && lane == __ffs(bm) - 1) s_T = inv_mono(klo + sel);
            }
        } else {
            need_fb = true;                        // block-uniform (m from SMEM)
        }
    }
    __syncthreads();

    if (need_fb) {
        // ---- Fallback: exact 32-bit bisection over register data (rare) ----
        unsigned pfx = 0;
        for (int bit = 31; bit >= 0; bit--) {
            const unsigned cand = pfx | (1u << bit);
            int c = 0;
#pragma unroll
            for (int i = 0; i < VPT; i++) {
                c += (mono(v[i].x) >= cand) + (mono(v[i].y) >= cand)
                   + (mono(v[i].z) >= cand) + (mono(v[i].w) >= cand);
            }
#pragma unroll
            for (int off = 16; off; off >>= 1) c += __shfl_down_sync(0xFFFFFFFFu, c, off);
            __syncthreads();
            if (tid == 0) s_cnt = 0;
            __syncthreads();
            if (lane == 0) atomicAdd(&s_cnt, c);
            __syncthreads();
            if ((unsigned)s_cnt >= r) pfx = cand;
        }
        if (tid == 0) s_T = inv_mono(pfx);
        __syncthreads();
    }
    const float T = s_T;

    // ---- Phase 5: mask from registers, single global write ----
#pragma unroll
    for (int i = 0; i < VPT; i++) {
        float4 o;
        o.x = v[i].x > T ? v[i].x : 0.0f;
        o.y = v[i].y > T ? v[i].y : 0.0f;
        o.z = v[i].z > T ? v[i].z : 0.0f;
        o.w = v[i].w > T ? v[i].w : 0.0f;
        op[tid + i * NT] = o;
    }
}

extern "C" void kernel_launch(void* const* d_in, const int* in_sizes, int n_in,
                              void* d_out, int out_size) {
    const float* in = (const float*)d_in[0];
    const int*   kp = (n_in >= 2) ? (const int*)d_in[1] : nullptr;
    float* out = (float*)d_out;
    const int rows = in_sizes[0] / COLS;
    ksparse_kernel<<<rows, NT>>>(in, kp, out);
}

// round 13
// speedup vs baseline: 1.3824x; 1.3824x over previous
#include <cuda_runtime.h>

#define NT   256          // threads per CTA
#define VPT  8            // float4 vectors per thread (8*4*256 = 8192)
#define COLS 8192         // row length
#define CAP  2048         // SMEM candidate buffer capacity
#define GCAP 128          // gather capacity for the hit bin

// Monotone mapping: float -> uint32 such that float order == unsigned order.
__device__ __forceinline__ unsigned mono(float f) {
    unsigned u = __float_as_uint(f);
    return (u & 0x80000000u) ? ~u : (u | 0x80000000u);
}

// Inverse of mono(). Clamps NaN bit patterns to +-inf.
__device__ __forceinline__ float inv_mono(unsigned k) {
    unsigned u = (k & 0x80000000u) ? (k & 0x7FFFFFFFu) : ~k;
    if ((u & 0x7F800000u) == 0x7F800000u && (u & 0x007FFFFFu))
        u = (u & 0x80000000u) | 0x7F800000u;
    return __uint_as_float(u);
}

// Single-warp collective: walk a 1024-bin histogram from the TOP bin down, find
// the bin where the cumulative count first reaches rr. All 32 lanes must call.
__device__ __forceinline__ void rank_walk(const unsigned* hist, unsigned rr, int lane,
                                          unsigned& bin_out, unsigned& nr_out) {
    const int base = 1024 - 32 * (lane + 1);   // lane 0 owns the TOP 32 bins
    unsigned s = 0;
#pragma unroll
    for (int i = 0; i < 32; i++) s += hist[base + i];
    unsigned p = s, t;
    t = __shfl_up_sync(0xFFFFFFFFu, p, 1);  if (lane >= 1)  p += t;
    t = __shfl_up_sync(0xFFFFFFFFu, p, 2);  if (lane >= 2)  p += t;
    t = __shfl_up_sync(0xFFFFFFFFu, p, 4);  if (lane >= 4)  p += t;
    t = __shfl_up_sync(0xFFFFFFFFu, p, 8);  if (lane >= 8)  p += t;
    t = __shfl_up_sync(0xFFFFFFFFu, p, 16); if (lane >= 16) p += t;
    const unsigned excl = p - s;
    const bool hit = (excl < rr) && (rr <= p);
    const unsigned m = __ballot_sync(0xFFFFFFFFu, hit);
    unsigned bin = 0, nr = rr;
    if (m) {
        const int hl = __ffs(m) - 1;
        if (lane == hl) {
            unsigned cum = excl;
            for (int b = base + 31; b >= base; b--) {
                cum += hist[b];
                if (cum >= rr) { bin = (unsigned)b; nr = rr - (cum - hist[b]); break; }
            }
        }
        bin = __shfl_sync(0xFFFFFFFFu, bin, hl);
        nr  = __shfl_sync(0xFFFFFFFFu, nr, hl);
    }
    bin_out = bin; nr_out = nr;
}

__global__ void __launch_bounds__(NT, 4) ksparse_kernel(const float* __restrict__ in,
                                                        const int* __restrict__ kp,
                                                        float* __restrict__ out) {
    __shared__ unsigned buf[CAP];      // 8 KB: klo-relative candidate keys
    __shared__ unsigned hist[1024];    // 4 KB
    __shared__ unsigned g[GCAP];       // hit-bin gather
    __shared__ unsigned warpsum[8];
    __shared__ int s_cnt, s_gn;
    __shared__ unsigned s_bin, s_rank;
    __shared__ float s_T;

    const int tid  = threadIdx.x;
    const int lane = tid & 31;
    const int wid  = tid >> 5;

    const float4* rp = (const float4*)(in  + (size_t)blockIdx.x * COLS);
    float4*       op = (float4*)      (out + (size_t)blockIdx.x * COLS);

    // Entire row resident in registers: one global read.
    float4 v[VPT];
#pragma unroll
    for (int i = 0; i < VPT; i++) v[i] = rp[tid + i * NT];

    const int K = kp ? __ldg(kp) : 512;
    const unsigned r = (unsigned)(K + 1);   // rank of threshold (descending, 1-indexed)

    // ---- Analytic pivot: U_lo below T with large margin (no samples, no SMEM).
    // Distribution assumption affects ONLY performance; the guards below route
    // any mismatch to the exact fallback.
    float p = (2.5f * (float)r + 160.0f) / (float)COLS;
    p = fminf(0.499f, fmaxf(p, 0.015625f));
    const float U_lo = normcdfinvf(1.0f - p);
    const unsigned klo = mono(U_lo);

    // ---- Phase 3a: single-compare mask over registers ----
    unsigned mbr = 0;
#pragma unroll
    for (int i = 0; i < VPT; i++) {
#pragma unroll
        for (int j = 0; j < 4; j++)
            mbr |= ((unsigned)((&v[i].x)[j] > U_lo)) << (i * 4 + j);
    }

    // Zero per-row state; ordered before use by the scan's barriers.
    hist[tid] = 0; hist[tid + NT] = 0; hist[tid + 2 * NT] = 0; hist[tid + 3 * NT] = 0;
    if (tid == 0) s_gn = 0;

    // Block scan of candidate counts -> total nbuf + per-thread offset.
    const unsigned cnt = (unsigned)__popc(mbr);
    unsigned inc = cnt, t;
    t = __shfl_up_sync(0xFFFFFFFFu, inc, 1);  if (lane >= 1)  inc += t;
    t = __shfl_up_sync(0xFFFFFFFFu, inc, 2);  if (lane >= 2)  inc += t;
    t = __shfl_up_sync(0xFFFFFFFFu, inc, 4);  if (lane >= 4)  inc += t;
    t = __shfl_up_sync(0xFFFFFFFFu, inc, 8);  if (lane >= 8)  inc += t;
    t = __shfl_up_sync(0xFFFFFFFFu, inc, 16); if (lane >= 16) inc += t;
    if (lane == 31) warpsum[wid] = inc;
    __syncthreads();
    if (wid == 0) {
        unsigned w = (lane < 8) ? warpsum[lane] : 0;
        t = __shfl_up_sync(0xFFFFFFFFu, w, 1); if (lane >= 1) w += t;
        t = __shfl_up_sync(0xFFFFFFFFu, w, 2); if (lane >= 2) w += t;
        t = __shfl_up_sync(0xFFFFFFFFu, w, 4); if (lane >= 4) w += t;
        if (lane < 8) warpsum[lane] = w;
    }
    __syncthreads();
    const int nbuf = (int)warpsum[7];
    int pos = (int)((wid ? warpsum[wid - 1] : 0u) + inc - cnt);

    // ---- Phase 3b: push klo-relative keys AND build the 10-bit histogram in
    // the same predicated loop (hist counts ALL candidates; buf overflow only
    // matters if nbuf > CAP, which routes to the fallback anyway).
#pragma unroll
    for (int i = 0; i < VPT; i++) {
#pragma unroll
        for (int j = 0; j < 4; j++) {
            if ((mbr >> (i * 4 + j)) & 1u) {
                const unsigned d = mono((&v[i].x)[j]) - klo;   // >= 1, no wrap
                if (pos < CAP) buf[pos] = d;
                unsigned dig = d >> 14;
                dig = dig > 1023u ? 1023u : dig;               // clamp: monotone
                atomicAdd(&hist[dig], 1u);
                pos++;
            }
        }
    }
    __syncthreads();

    const bool ok = (nbuf <= CAP) && ((int)r <= nbuf);
    bool need_fb = !ok;                            // block-uniform

    if (ok) {
        // ---- Phase 4a: rank r over the (already built) 1024-bin histogram ----
        if (wid == 0) {
            unsigned b, nr;
            rank_walk(hist, r, lane, b, nr);
            if (lane == 0) { s_bin = b; s_rank = nr; }
        }
        __syncthreads();
        const unsigned bin = s_bin;
        const unsigned nr  = s_rank;
        const int m = (int)hist[bin];
        if (m <= GCAP) {
            // ---- Phase 4b: gather hit-bin keys from the dense buffer ----
            for (int i = tid; i < nbuf; i += NT) {
                const unsigned d = buf[i];
                unsigned dig = d >> 14;
                dig = dig > 1023u ? 1023u : dig;
                if (dig == bin) {
                    const int pg = atomicAdd(&s_gn, 1);
                    if (pg < GCAP) g[pg] = d;
                }
            }
            __syncthreads();
            // ---- Phase 4c: warp 0 selects the nr-th largest among m keys ----
            if (wid == 0) {
                if (m <= 32) {
                    // Shuffle fast path: no LDS in the serial loop.
                    const unsigned key = (lane < m) ? g[lane] : 0u;
                    int gt = 0, ge = 0;
#pragma unroll
                    for (int i = 0; i < 32; i++) {
                        const unsigned ki = __shfl_sync(0xFFFFFFFFu, key, i);
                        const bool valid = (i < m);
                        gt += (valid && (ki > key));
                        ge += (valid && (ki >= key));
                    }
                    const bool hit = (lane < m) &&
                                     ((unsigned)gt < nr) && (nr <= (unsigned)ge);
                    const unsigned bm = __ballot_sync(0xFFFFFFFFu, hit);
                    if (bm && lane == __ffs(bm) - 1) s_T = inv_mono(klo + key);
                } else {
                    unsigned my[4]; int gt[4] = {0,0,0,0}, ge[4] = {0,0,0,0};
#pragma unroll
                    for (int q = 0; q < 4; q++)
                        my[q] = (lane + 32 * q < m) ? g[lane + 32 * q] : 0u;
                    for (int i = 0; i < m; i++) {
                        const unsigned ki = g[i];
#pragma unroll
                        for (int q = 0; q < 4; q++) {
                            gt[q] += (ki > my[q]);
                            ge[q] += (ki >= my[q]);
                        }
                    }
                    bool found = false; unsigned sel = 0;
#pragma unroll
                    for (int q = 0; q < 4; q++) {
                        const bool hit = (lane + 32 * q < m) &&
                                         ((unsigned)gt[q] < nr) && (nr <= (unsigned)ge[q]);
                        if (hit && !found) { sel = my[q]; found = true; }
                    }
                    const unsigned bm = __ballot_sync(0xFFFFFFFFu, found);
                    if (bm && lane == __ffs(bm) - 1) s_T = inv_mono(klo + sel);
                }
            }
        } else {
            need_fb = true;                        // block-uniform (m from SMEM)
        }
    }
    __syncthreads();

    if (need_fb) {
        // ---- Fallback: exact 32-bit bisection over register data (rare) ----
        unsigned pfx = 0;
        for (int bit = 31; bit >= 0; bit--) {
            const unsigned cand = pfx | (1u << bit);
            int c = 0;
#pragma unroll
            for (int i = 0; i < VPT; i++) {
                c += (mono(v[i].x) >= cand) + (mono(v[i].y) >= cand)
                   + (mono(v[i].z) >= cand) + (mono(v[i].w) >= cand);
            }
#pragma unroll
            for (int off = 16; off; off >>= 1) c += __shfl_down_sync(0xFFFFFFFFu, c, off);
            __syncthreads();
            if (tid == 0) s_cnt = 0;
            __syncthreads();
            if (lane == 0) atomicAdd(&s_cnt, c);
            __syncthreads();
            if ((unsigned)s_cnt >= r) pfx = cand;
        }
        if (tid == 0) s_T = inv_mono(pfx);
        __syncthreads();
    }
    const float T = s_T;

    // ---- Phase 5: mask from registers, single global write ----
#pragma unroll
    for (int i = 0; i < VPT; i++) {
        float4 o;
        o.x = v[i].x > T ? v[i].x : 0.0f;
        o.y = v[i].y > T ? v[i].y : 0.0f;
        o.z = v[i].z > T ? v[i].z : 0.0f;
        o.w = v[i].w > T ? v[i].w : 0.0f;
        op[tid + i * NT] = o;
    }
}

extern "C" void kernel_launch(void* const* d_in, const int* in_sizes, int n_in,
                              void* d_out, int out_size) {
    const float* in = (const float*)d_in[0];
    const int*   kp = (n_in >= 2) ? (const int*)d_in[1] : nullptr;
    float* out = (float*)d_out;
    const int rows = in_sizes[0] / COLS;
    ksparse_kernel<<<rows, NT>>>(in, kp, out);
}

// round 14
// speedup vs baseline: 1.4439x; 1.0445x over previous
#include <cuda_runtime.h>

#define NT   256          // threads per CTA
#define VPT  8            // float4 vectors per thread (8*4*256 = 8192)
#define COLS 8192         // row length
#define WCAP 256          // per-warp candidate capacity (8 warps -> 2048 total)
#define GCAP 128          // gather capacity for the hit bin

// Monotone mapping: float -> uint32 such that float order == unsigned order.
__device__ __forceinline__ unsigned mono(float f) {
    unsigned u = __float_as_uint(f);
    return (u & 0x80000000u) ? ~u : (u | 0x80000000u);
}

// Inverse of mono(). Clamps NaN bit patterns to +-inf.
__device__ __forceinline__ float inv_mono(unsigned k) {
    unsigned u = (k & 0x80000000u) ? (k & 0x7FFFFFFFu) : ~k;
    if ((u & 0x7F800000u) == 0x7F800000u && (u & 0x007FFFFFu))
        u = (u & 0x80000000u) | 0x7F800000u;
    return __uint_as_float(u);
}

// Single-warp collective: walk a 512-bin histogram from the TOP bin down, find
// the bin where the cumulative count first reaches rr. All 32 lanes must call.
__device__ __forceinline__ void rank_walk512(const unsigned* hist, unsigned rr, int lane,
                                             unsigned& bin_out, unsigned& nr_out) {
    const int base = 512 - 16 * (lane + 1);    // lane 0 owns the TOP 16 bins
    unsigned s = 0;
#pragma unroll
    for (int i = 0; i < 16; i++) s += hist[base + i];
    unsigned p = s, t;
    t = __shfl_up_sync(0xFFFFFFFFu, p, 1);  if (lane >= 1)  p += t;
    t = __shfl_up_sync(0xFFFFFFFFu, p, 2);  if (lane >= 2)  p += t;
    t = __shfl_up_sync(0xFFFFFFFFu, p, 4);  if (lane >= 4)  p += t;
    t = __shfl_up_sync(0xFFFFFFFFu, p, 8);  if (lane >= 8)  p += t;
    t = __shfl_up_sync(0xFFFFFFFFu, p, 16); if (lane >= 16) p += t;
    const unsigned excl = p - s;
    const bool hit = (excl < rr) && (rr <= p);
    const unsigned m = __ballot_sync(0xFFFFFFFFu, hit);
    unsigned bin = 0, nr = rr;
    if (m) {
        const int hl = __ffs(m) - 1;
        if (lane == hl) {
            unsigned cum = excl;
            for (int b = base + 15; b >= base; b--) {
                cum += hist[b];
                if (cum >= rr) { bin = (unsigned)b; nr = rr - (cum - hist[b]); break; }
            }
        }
        bin = __shfl_sync(0xFFFFFFFFu, bin, hl);
        nr  = __shfl_sync(0xFFFFFFFFu, nr, hl);
    }
    bin_out = bin; nr_out = nr;
}

__global__ void __launch_bounds__(NT, 4) ksparse_kernel(const float* __restrict__ in,
                                                        const int* __restrict__ kp,
                                                        float* __restrict__ out) {
    __shared__ unsigned buf[8][WCAP];  // 8 KB: per-warp klo-relative keys
    __shared__ unsigned hist[512];     // 2 KB
    __shared__ unsigned g[GCAP];       // hit-bin gather
    __shared__ unsigned warpcnt[8];
    __shared__ int s_cnt, s_gn;
    __shared__ unsigned s_bin, s_rank;
    __shared__ float s_T;

    const int tid  = threadIdx.x;
    const int lane = tid & 31;
    const int wid  = tid >> 5;

    const float4* rp = (const float4*)(in  + (size_t)blockIdx.x * COLS);
    float4*       op = (float4*)      (out + (size_t)blockIdx.x * COLS);

    // Entire row resident in registers: one global read (streaming hint).
    float4 v[VPT];
#pragma unroll
    for (int i = 0; i < VPT; i++) v[i] = __ldcs(rp + tid + i * NT);

    const int K = kp ? __ldg(kp) : 512;
    const unsigned r = (unsigned)(K + 1);   // rank of threshold (descending, 1-indexed)

    // ---- Analytic pivot (pure ALU; overlaps the loads). Distribution
    // assumption affects ONLY performance; guards route any mismatch to the
    // exact fallback.
    float p = (2.5f * (float)r + 160.0f) / (float)COLS;
    p = fminf(0.499f, fmaxf(p, 0.015625f));
    const float U_lo = normcdfinvf(1.0f - p);
    const unsigned klo = mono(U_lo);

    // Zero per-row state and sync NOW — this barrier hides under the LDG
    // latency (syncthreads waits for warp arrival, not outstanding loads).
    hist[tid & 511] = 0;           // tid 0..255 -> bins 0..255; next line covers rest
    hist[(tid & 255) + 256] = 0;
    if (tid == 0) s_gn = 0;
    __syncthreads();

    // ---- Phase 3a: single-compare mask over registers ----
    unsigned mbr = 0;
#pragma unroll
    for (int i = 0; i < VPT; i++) {
#pragma unroll
        for (int j = 0; j < 4; j++)
            mbr |= ((unsigned)((&v[i].x)[j] > U_lo)) << (i * 4 + j);
    }

    // Warp-local exclusive scan of candidate counts (no block barriers).
    const unsigned cnt = (unsigned)__popc(mbr);
    unsigned inc = cnt, t;
    t = __shfl_up_sync(0xFFFFFFFFu, inc, 1);  if (lane >= 1)  inc += t;
    t = __shfl_up_sync(0xFFFFFFFFu, inc, 2);  if (lane >= 2)  inc += t;
    t = __shfl_up_sync(0xFFFFFFFFu, inc, 4);  if (lane >= 4)  inc += t;
    t = __shfl_up_sync(0xFFFFFFFFu, inc, 8);  if (lane >= 8)  inc += t;
    t = __shfl_up_sync(0xFFFFFFFFu, inc, 16); if (lane >= 16) inc += t;
    if (lane == 31) warpcnt[wid] = inc;
    int pos = (int)(inc - cnt);

    // ---- Phase 3b: push keys into the warp's own segment + build histogram
    // in the same predicated loop (hist counts ALL candidates; segment
    // overflow routes to the fallback via the maxw guard).
#pragma unroll
    for (int i = 0; i < VPT; i++) {
#pragma unroll
        for (int j = 0; j < 4; j++) {
            if ((mbr >> (i * 4 + j)) & 1u) {
                const unsigned d = mono((&v[i].x)[j]) - klo;   // >= 1, no wrap
                if (pos < WCAP) buf[wid][pos] = d;
                unsigned dig = d >> 15;
                dig = dig > 511u ? 511u : dig;                 // clamp: monotone
                atomicAdd(&hist[dig], 1u);
                pos++;
            }
        }
    }
    __syncthreads();

    // Guards (uniform across the block).
    unsigned nbuf = 0, maxw = 0;
#pragma unroll
    for (int w = 0; w < 8; w++) {
        const unsigned c = warpcnt[w];
        nbuf += c;
        maxw = c > maxw ? c : maxw;
    }
    const bool ok = (maxw <= WCAP) && (r <= nbuf);
    bool need_fb = !ok;

    if (ok) {
        // ---- Phase 4a: rank r over the 512-bin histogram ----
        if (wid == 0) {
            unsigned b, nr;
            rank_walk512(hist, r, lane, b, nr);
            if (lane == 0) { s_bin = b; s_rank = nr; }
        }
        __syncthreads();
        const unsigned bin = s_bin;
        const unsigned nr  = s_rank;
        const int m = (int)hist[bin];
        if (m <= GCAP) {
            // ---- Phase 4b: gather hit-bin keys from the per-warp segments ----
#pragma unroll
            for (int q = 0; q < 8 * WCAP / NT; q++) {
                const int i = tid + q * NT;
                const int w = i >> 8, s = i & (WCAP - 1);
                if ((unsigned)s < warpcnt[w]) {
                    const unsigned d = buf[w][s];
                    unsigned dig = d >> 15;
                    dig = dig > 511u ? 511u : dig;
                    if (dig == bin) {
                        const int pg = atomicAdd(&s_gn, 1);
                        if (pg < GCAP) g[pg] = d;
                    }
                }
            }
            __syncthreads();
            // ---- Phase 4c: warp 0 selects the nr-th largest among m keys ----
            if (wid == 0) {
                if (m <= 32) {
                    const unsigned key = (lane < m) ? g[lane] : 0u;
                    int gt = 0, ge = 0;
#pragma unroll
                    for (int i = 0; i < 32; i++) {
                        const unsigned ki = __shfl_sync(0xFFFFFFFFu, key, i);
                        const bool valid = (i < m);
                        gt += (valid && (ki > key));
                        ge += (valid && (ki >= key));
                    }
                    const bool hit = (lane < m) &&
                                     ((unsigned)gt < nr) && (nr <= (unsigned)ge);
                    const unsigned bm = __ballot_sync(0xFFFFFFFFu, hit);
                    if (bm && lane == __ffs(bm) - 1) s_T = inv_mono(klo + key);
                } else {
                    unsigned my[4]; int gt[4] = {0,0,0,0}, ge[4] = {0,0,0,0};
#pragma unroll
                    for (int q = 0; q < 4; q++)
                        my[q] = (lane + 32 * q < m) ? g[lane + 32 * q] : 0u;
                    for (int i = 0; i < m; i++) {
                        const unsigned ki = g[i];
#pragma unroll
                        for (int q = 0; q < 4; q++) {
                            gt[q] += (ki > my[q]);
                            ge[q] += (ki >= my[q]);
                        }
                    }
                    bool found = false; unsigned sel = 0;
#pragma unroll
                    for (int q = 0; q < 4; q++) {
                        const bool hit = (lane + 32 * q < m) &&
                                         ((unsigned)gt[q] < nr) && (nr <= (unsigned)ge[q]);
                        if (hit && !found) { sel = my[q]; found = true; }
                    }
                    const unsigned bm = __ballot_sync(0xFFFFFFFFu, found);
                    if (bm && lane == __ffs(bm) - 1) s_T = inv_mono(klo + sel);
                }
            }
        } else {
            need_fb = true;                        // block-uniform (m from SMEM)
        }
    }
    __syncthreads();

    if (need_fb) {
        // ---- Fallback: exact 32-bit bisection over register data (rare) ----
        unsigned pfx = 0;
        for (int bit = 31; bit >= 0; bit--) {
            const unsigned cand = pfx | (1u << bit);
            int c = 0;
#pragma unroll
            for (int i = 0; i < VPT; i++) {
                c += (mono(v[i].x) >= cand) + (mono(v[i].y) >= cand)
                   + (mono(v[i].z) >= cand) + (mono(v[i].w) >= cand);
            }
#pragma unroll
            for (int off = 16; off; off >>= 1) c += __shfl_down_sync(0xFFFFFFFFu, c, off);
            __syncthreads();
            if (tid == 0) s_cnt = 0;
            __syncthreads();
            if (lane == 0) atomicAdd(&s_cnt, c);
            __syncthreads();
            if ((unsigned)s_cnt >= r) pfx = cand;
        }
        if (tid == 0) s_T = inv_mono(pfx);
        __syncthreads();
    }
    const float T = s_T;

    // ---- Phase 5: mask from registers, single streaming global write ----
#pragma unroll
    for (int i = 0; i < VPT; i++) {
        float4 o;
        o.x = v[i].x > T ? v[i].x : 0.0f;
        o.y = v[i].y > T ? v[i].y : 0.0f;
        o.z = v[i].z > T ? v[i].z : 0.0f;
        o.w = v[i].w > T ? v[i].w : 0.0f;
        __stcs(op + tid + i * NT, o);
    }
}

extern "C" void kernel_launch(void* const* d_in, const int* in_sizes, int n_in,
                              void* d_out, int out_size) {
    const float* in = (const float*)d_in[0];
    const int*   kp = (n_in >= 2) ? (const int*)d_in[1] : nullptr;
    float* out = (float*)d_out;
    const int rows = in_sizes[0] / COLS;
    ksparse_kernel<<<rows, NT>>>(in, kp, out);
}